// round 15
// baseline (speedup 1.0000x reference)
#include <cuda_runtime.h>
#include <cstdint>

// pred:  (64, 512, 512) fp32   -> d_in[0]
// label: (64, 1, 512, 512) fp32 -> d_in[1]
// out:   scalar fp32
//
// TMA-style bulk-copy pipeline: cp.async.bulk (UBLKCP) streams pred/label
// stages into shared memory behind an mbarrier; compute warps consume from
// smem. In-flight bytes are set by pipeline depth x blocks/SM, not by warp
// count -- this attacks the R3..R14 finding that DRAM% tracked warp count
// because per-warp LDG MLP saturated at ~2.
// Last-finishing block (atomic ticket) reduces all partials.

#define BATCHES     64
#define N_ELEM      (512 * 512)          // per batch
#define BPB         32                   // chunks per batch
#define TPB         256
#define NBLK        (BATCHES * BPB)      // 2048
#define CHUNK_FLOATS (N_ELEM / BPB)      // 8192 floats per array per chunk
#define STAGE_FLOATS 2048                // 8KB per array per stage
#define NSTAGES     (CHUNK_FLOATS / STAGE_FLOATS)  // 4
#define DEPTH       2
#define STAGE_BYTES (STAGE_FLOATS * 4)   // 8192
#define F4_PER_STAGE (STAGE_FLOATS / 4)  // 512
#define F4_PER_THREAD (F4_PER_STAGE / TPB) // 2

__device__ double g_mse [NBLK];
__device__ float  g_pval[NBLK];
__device__ int    g_pidx[NBLK];
__device__ float  g_lval[NBLK];
__device__ int    g_lidx[NBLK];
__device__ int    g_ticket = 0;

// ---- PTX helpers --------------------------------------------------------
__device__ __forceinline__ void mbar_init(uint32_t addr, uint32_t count) {
    asm volatile("mbarrier.init.shared.b64 [%0], %1;" :: "r"(addr), "r"(count) : "memory");
}
__device__ __forceinline__ void mbar_expect_tx(uint32_t addr, uint32_t tx) {
    asm volatile("mbarrier.arrive.expect_tx.shared.b64 _, [%0], %1;"
                 :: "r"(addr), "r"(tx) : "memory");
}
__device__ __forceinline__ void bulk_g2s(uint32_t dst, const void* src,
                                         uint32_t bytes, uint32_t mbar) {
    asm volatile(
        "cp.async.bulk.shared::cluster.global.mbarrier::complete_tx::bytes "
        "[%0], [%1], %2, [%3];"
        :: "r"(dst), "l"(src), "r"(bytes), "r"(mbar) : "memory");
}
__device__ __forceinline__ void mbar_wait(uint32_t mbar, uint32_t parity) {
    uint32_t done;
    asm volatile(
        "{\n\t"
        ".reg .pred p;\n\t"
        "mbarrier.try_wait.parity.acquire.cta.shared::cta.b64 p, [%1], %2;\n\t"
        "selp.b32 %0, 1, 0, p;\n\t"
        "}"
        : "=r"(done) : "r"(mbar), "r"(parity) : "memory");
    if (!done) {
        asm volatile(
            "{\n\t"
            ".reg .pred P1;\n\t"
            "WAIT_LOOP_%=:\n\t"
            "mbarrier.try_wait.parity.acquire.cta.shared::cta.b64 P1, [%0], %1, 0x989680;\n\t"
            "@P1 bra.uni WAIT_DONE_%=;\n\t"
            "bra.uni WAIT_LOOP_%=;\n\t"
            "WAIT_DONE_%=:\n\t"
            "}"
            :: "r"(mbar), "r"(parity) : "memory");
    }
}
// -------------------------------------------------------------------------

union SmemU {
    struct {
        float p[DEPTH][STAGE_FLOATS];
        float l[DEPTH][STAGE_FLOATS];
    } pipe;                                   // 32 KB
    struct {                                  // reduction overlay (used after pipe is dead)
        float  pv[TPB]; int pi[TPB];
        float  lv[TPB]; int li[TPB];
        double m [TPB];
        double fm[TPB];
        double fidx[BATCHES];
    } red;
};

__global__ void __launch_bounds__(TPB) fused(const float* __restrict__ pred,
                                             const float* __restrict__ label,
                                             float* __restrict__ out)
{
    __shared__ SmemU u;
    __shared__ alignas(8) unsigned long long mb_full_storage[DEPTH];

    const int blk = blockIdx.x;        // 0..2047
    const int b   = blk >> 5;          // batch
    const int sub = blk & 31;          // chunk within batch
    const int t   = threadIdx.x;

    const uint32_t mbf0 = (uint32_t)__cvta_generic_to_shared(&mb_full_storage[0]);
    uint32_t sp[DEPTH], sl[DEPTH];
    #pragma unroll
    for (int d = 0; d < DEPTH; d++) {
        sp[d] = (uint32_t)__cvta_generic_to_shared(&u.pipe.p[d][0]);
        sl[d] = (uint32_t)__cvta_generic_to_shared(&u.pipe.l[d][0]);
    }

    // chunk base (in floats) within the flat (64*512*512) arrays
    const size_t chunk_f = (size_t)b * N_ELEM + (size_t)sub * CHUNK_FLOATS;
    const int    eoff0   = sub * CHUNK_FLOATS;   // element index base within image

    if (t == 0) {
        #pragma unroll
        for (int d = 0; d < DEPTH; d++) mbar_init(mbf0 + d * 8, 1);
    }
    __syncthreads();

    // Prologue: fill both slots
    if (t == 0) {
        #pragma unroll
        for (int s = 0; s < DEPTH; s++) {
            mbar_expect_tx(mbf0 + s * 8, 2 * STAGE_BYTES);
            bulk_g2s(sp[s], pred  + chunk_f + (size_t)s * STAGE_FLOATS, STAGE_BYTES, mbf0 + s * 8);
            bulk_g2s(sl[s], label + chunk_f + (size_t)s * STAGE_FLOATS, STAGE_BYTES, mbf0 + s * 8);
        }
    }

    float pv = -3.402823466e38f; int pi = 0;
    float lv = -3.402823466e38f; int li = 0;
    float m0 = 0.0f, m1 = 0.0f, m2 = 0.0f, m3 = 0.0f;

    #pragma unroll
    for (int s = 0; s < NSTAGES; s++) {
        const int slot = s & (DEPTH - 1);
        mbar_wait(mbf0 + slot * 8, (s / DEPTH) & 1);

        const float4* Pbuf = (const float4*)&u.pipe.p[slot][0];
        const float4* Lbuf = (const float4*)&u.pipe.l[slot][0];

        #pragma unroll
        for (int j = 0; j < F4_PER_THREAD; j++) {
            const int f4 = t + j * TPB;                       // ascending in j
            const float4 p = Pbuf[f4];
            const float4 l = Lbuf[f4];
            const int e = eoff0 + s * STAGE_FLOATS + f4 * 4;  // ascending in s,j
            // strict > keeps the FIRST max
            if (p.x > pv) { pv = p.x; pi = e;     }
            if (p.y > pv) { pv = p.y; pi = e + 1; }
            if (p.z > pv) { pv = p.z; pi = e + 2; }
            if (p.w > pv) { pv = p.w; pi = e + 3; }
            if (l.x > lv) { lv = l.x; li = e;     }
            if (l.y > lv) { lv = l.y; li = e + 1; }
            if (l.z > lv) { lv = l.z; li = e + 2; }
            if (l.w > lv) { lv = l.w; li = e + 3; }
            const float dx = p.x - l.x;
            const float dy = p.y - l.y;
            const float dz = p.z - l.z;
            const float dw = p.w - l.w;
            m0 += dx * dx; m1 += dy * dy; m2 += dz * dz; m3 += dw * dw;
        }

        __syncthreads();   // everyone consumed this slot -> safe to refill
        if (t == 0 && s + DEPTH < NSTAGES) {
            const int ns = s + DEPTH;
            mbar_expect_tx(mbf0 + slot * 8, 2 * STAGE_BYTES);
            bulk_g2s(sp[slot], pred  + chunk_f + (size_t)ns * STAGE_FLOATS, STAGE_BYTES, mbf0 + slot * 8);
            bulk_g2s(sl[slot], label + chunk_f + (size_t)ns * STAGE_FLOATS, STAGE_BYTES, mbf0 + slot * 8);
        }
    }
    const float mse = (m0 + m1) + (m2 + m3);

    __syncthreads();   // pipeline fully consumed -> reuse smem for reduction
    u.red.pv[t] = pv; u.red.pi[t] = pi;
    u.red.lv[t] = lv; u.red.li[t] = li;
    u.red.m [t] = (double)mse;
    __syncthreads();

    for (int s = TPB / 2; s > 0; s >>= 1) {
        if (t < s) {
            if (u.red.pv[t+s] > u.red.pv[t] ||
                (u.red.pv[t+s] == u.red.pv[t] && u.red.pi[t+s] < u.red.pi[t])) {
                u.red.pv[t] = u.red.pv[t+s]; u.red.pi[t] = u.red.pi[t+s];
            }
            if (u.red.lv[t+s] > u.red.lv[t] ||
                (u.red.lv[t+s] == u.red.lv[t] && u.red.li[t+s] < u.red.li[t])) {
                u.red.lv[t] = u.red.lv[t+s]; u.red.li[t] = u.red.li[t+s];
            }
            u.red.m[t] += u.red.m[t+s];
        }
        __syncthreads();
    }

    __shared__ bool isLast;
    if (t == 0) {
        g_mse [blk] = u.red.m[0];
        g_pval[blk] = u.red.pv[0]; g_pidx[blk] = u.red.pi[0];
        g_lval[blk] = u.red.lv[0]; g_lidx[blk] = u.red.li[0];
        __threadfence();
        const int ticket = atomicAdd(&g_ticket, 1);
        isLast = (ticket == NBLK - 1);
    }
    __syncthreads();
    if (!isLast) return;

    // ---- final reduction in the last-finishing block ----
    {
        double s0 = 0.0;
        #pragma unroll
        for (int j = 0; j < NBLK / TPB; j++) s0 += g_mse[t * (NBLK / TPB) + j];
        u.red.fm[t] = s0;
    }

    if (t < BATCHES) {
        float ppv = -3.402823466e38f; int ppi = 0;
        float llv = -3.402823466e38f; int lli = 0;
        #pragma unroll
        for (int p = 0; p < BPB; p++) {
            const int j = t * BPB + p;   // chunks in ascending index order
            float v = g_pval[j]; int i = g_pidx[j];
            if (v > ppv || (v == ppv && i < ppi)) { ppv = v; ppi = i; }
            v = g_lval[j]; i = g_lidx[j];
            if (v > llv || (v == llv && i < lli)) { llv = v; lli = i; }
        }
        const float rp = (float)(ppi >> 9), cp = (float)(ppi & 511);
        const float rl = (float)(lli >> 9), cl = (float)(lli & 511);
        const float dr = rp - rl, dc = cp - cl;
        u.red.fidx[t] = (double)(dr * dr) + (double)(dc * dc);
    }
    __syncthreads();

    for (int s = TPB / 2; s > 0; s >>= 1) {
        if (t < s) u.red.fm[t] += u.red.fm[t + s];
        __syncthreads();
    }
    for (int s = BATCHES / 2; s > 0; s >>= 1) {
        if (t < s) u.red.fidx[t] += u.red.fidx[t + s];
        __syncthreads();
    }

    if (t == 0) {
        g_ticket = 0;   // reset BEFORE the output store; next replay sees 0
        __threadfence();
        const double mseT = u.red.fm[0];
        const double il   = u.red.fidx[0];
        const double alpha = (il != 0.0) ? (mseT / il) : 1.0;
        const double loss  = (mseT + 0.25 * alpha * il) / (double)BATCHES;
        out[0] = (float)loss;
    }
}

extern "C" void kernel_launch(void* const* d_in, const int* in_sizes, int n_in,
                              void* d_out, int out_size)
{
    (void)in_sizes; (void)n_in; (void)out_size;
    const float* pred  = (const float*)d_in[0];
    const float* label = (const float*)d_in[1];
    float* out = (float*)d_out;

    fused<<<NBLK, TPB>>>(pred, label, out);
}

// round 16
// speedup vs baseline: 1.0008x; 1.0008x over previous
#include <cuda_runtime.h>

// pred:  (64, 512, 512) fp32   -> d_in[0]
// label: (64, 1, 512, 512) fp32 -> d_in[1]
// out:   scalar fp32
//
// R16: shorten the per-warp loop-carried chain. Per float4 the argmax is a
// 3-FMNMX tree (off the critical chain) + ONE compare/select of
// (vmax, float4_index) against the running max. The winning lane within the
// float4 is recovered AFTER the block reduction by re-loading that single
// float4 (thread 0). Low regs -> 8 blocks/SM; __ldcs for single-use data.
// Last-finishing block (atomic ticket) merges chunk partials.

#define BATCHES   64
#define N_ELEM    (512 * 512)
#define N_F4      (N_ELEM / 4)         // 65536 float4 per image
#define BPB       32                   // chunks (blocks) per image
#define TPB       256
#define NBLK      (BATCHES * BPB)      // 2048
#define F4_PER_SUB (N_F4 / BPB)        // 2048
#define ITERS     (F4_PER_SUB / TPB)   // 8

__device__ double g_mse [NBLK];
__device__ float  g_pval[NBLK];
__device__ int    g_pidx[NBLK];        // final element index within image
__device__ float  g_lval[NBLK];
__device__ int    g_lidx[NBLK];
__device__ int    g_ticket = 0;

__global__ void __launch_bounds__(TPB) fused(const float4* __restrict__ pred,
                                             const float4* __restrict__ label,
                                             float* __restrict__ out)
{
    const int blk = blockIdx.x;        // 0..2047
    const int b   = blk >> 5;          // image
    const int sub = blk & 31;          // chunk within image (ascending ranges)
    const int t   = threadIdx.x;

    const size_t imgbase = (size_t)b * N_F4;
    int f4 = sub * F4_PER_SUB + t;     // float4 index within image, ascending

    float pv = -3.402823466e38f; int pf4 = 0;   // running (max-of-4, float4 idx)
    float lv = -3.402823466e38f; int lf4 = 0;
    float m0 = 0.0f, m1 = 0.0f, m2 = 0.0f, m3 = 0.0f;

    #pragma unroll
    for (int k = 0; k < ITERS; k++) {
        const float4 p = __ldcs(&pred [imgbase + f4]);
        const float4 l = __ldcs(&label[imgbase + f4]);

        // 3-FMNMX tree per array: independent of the loop-carried chain
        const float pm = fmaxf(fmaxf(p.x, p.y), fmaxf(p.z, p.w));
        const float lm = fmaxf(fmaxf(l.x, l.y), fmaxf(l.z, l.w));
        // ONE compare/select on the carried chain; strict > keeps first f4
        if (pm > pv) { pv = pm; pf4 = f4; }
        if (lm > lv) { lv = lm; lf4 = f4; }

        const float dx = p.x - l.x;
        const float dy = p.y - l.y;
        const float dz = p.z - l.z;
        const float dw = p.w - l.w;
        m0 += dx * dx; m1 += dy * dy; m2 += dz * dz; m3 += dw * dw;

        f4 += TPB;
    }
    const float mse = (m0 + m1) + (m2 + m3);

    __shared__ float  sPv[TPB]; __shared__ int sPi[TPB];
    __shared__ float  sLv[TPB]; __shared__ int sLi[TPB];
    __shared__ double sM [TPB];
    sPv[t] = pv; sPi[t] = pf4;
    sLv[t] = lv; sLi[t] = lf4;
    sM[t]  = (double)mse;
    __syncthreads();

    // Block reduction: max value, tie -> smaller float4 index (= first max)
    for (int s = TPB / 2; s > 0; s >>= 1) {
        if (t < s) {
            if (sPv[t+s] > sPv[t] || (sPv[t+s] == sPv[t] && sPi[t+s] < sPi[t])) {
                sPv[t] = sPv[t+s]; sPi[t] = sPi[t+s];
            }
            if (sLv[t+s] > sLv[t] || (sLv[t+s] == sLv[t] && sLi[t+s] < sLi[t])) {
                sLv[t] = sLv[t+s]; sLi[t] = sLi[t+s];
            }
            sM[t] += sM[t+s];
        }
        __syncthreads();
    }

    __shared__ bool isLast;
    if (t == 0) {
        // Resolve the winning lane within each winning float4 (first equal lane)
        {
            const float4 wp = pred[imgbase + sPi[0]];
            const float  v  = sPv[0];
            int j = 3;
            if (wp.z == v) j = 2;
            if (wp.y == v) j = 1;
            if (wp.x == v) j = 0;
            g_pidx[blk] = sPi[0] * 4 + j;
            g_pval[blk] = v;
        }
        {
            const float4 wl = label[imgbase + sLi[0]];
            const float  v  = sLv[0];
            int j = 3;
            if (wl.z == v) j = 2;
            if (wl.y == v) j = 1;
            if (wl.x == v) j = 0;
            g_lidx[blk] = sLi[0] * 4 + j;
            g_lval[blk] = v;
        }
        g_mse[blk] = sM[0];
        __threadfence();
        const int ticket = atomicAdd(&g_ticket, 1);
        isLast = (ticket == NBLK - 1);
    }
    __syncthreads();
    if (!isLast) return;

    // ---- final reduction in the last-finishing block ----
    __shared__ double fM[TPB];
    __shared__ double fIdx[BATCHES];

    {
        double s0 = 0.0;
        #pragma unroll
        for (int j = 0; j < NBLK / TPB; j++) s0 += g_mse[t * (NBLK / TPB) + j];
        fM[t] = s0;
    }

    if (t < BATCHES) {
        float ppv = -3.402823466e38f; int ppi = 0;
        float llv = -3.402823466e38f; int lli = 0;
        #pragma unroll
        for (int p = 0; p < BPB; p++) {
            const int j = t * BPB + p;   // chunks in ascending index order
            float v = g_pval[j]; int i = g_pidx[j];
            if (v > ppv || (v == ppv && i < ppi)) { ppv = v; ppi = i; }
            v = g_lval[j]; i = g_lidx[j];
            if (v > llv || (v == llv && i < lli)) { llv = v; lli = i; }
        }
        const float rp = (float)(ppi >> 9), cp = (float)(ppi & 511);
        const float rl = (float)(lli >> 9), cl = (float)(lli & 511);
        const float dr = rp - rl, dc = cp - cl;
        fIdx[t] = (double)(dr * dr) + (double)(dc * dc);
    }
    __syncthreads();

    for (int s = TPB / 2; s > 0; s >>= 1) {
        if (t < s) fM[t] += fM[t + s];
        __syncthreads();
    }
    for (int s = BATCHES / 2; s > 0; s >>= 1) {
        if (t < s) fIdx[t] += fIdx[t + s];
        __syncthreads();
    }

    if (t == 0) {
        g_ticket = 0;   // reset BEFORE the output store; next replay sees 0
        __threadfence();
        const double mseT = fM[0];
        const double il   = fIdx[0];
        const double alpha = (il != 0.0) ? (mseT / il) : 1.0;
        const double loss  = (mseT + 0.25 * alpha * il) / (double)BATCHES;
        out[0] = (float)loss;
    }
}

extern "C" void kernel_launch(void* const* d_in, const int* in_sizes, int n_in,
                              void* d_out, int out_size)
{
    (void)in_sizes; (void)n_in; (void)out_size;
    const float4* pred  = (const float4*)d_in[0];
    const float4* label = (const float4*)d_in[1];
    float* out = (float*)d_out;

    fused<<<NBLK, TPB>>>(pred, label, out);
}

// round 17
// speedup vs baseline: 1.1339x; 1.1330x over previous
#include <cuda_runtime.h>

// pred:  (64, 512, 512) fp32   -> d_in[0]
// label: (64, 1, 512, 512) fp32 -> d_in[1]
// out:   scalar fp32
//
// R17 = R3's proven streaming config (grid=1024, 16 iters, interleaved loads,
// single wave @ ~8 blocks/SM) + R16's cheap per-iter argmax (FMNMX tree +
// one (max, f4idx) select; lane recovered post-reduction) + shuffle-based
// epilogue (1 barrier instead of 8). Last-finishing block merges partials.

#define BATCHES   64
#define N_ELEM    (512 * 512)
#define N_F4      (N_ELEM / 4)         // 65536 float4 per image
#define BPB       16                   // chunks (blocks) per image
#define TPB       256
#define NWARP     (TPB / 32)           // 8
#define NBLK      (BATCHES * BPB)      // 1024
#define F4_PER_SUB (N_F4 / BPB)        // 4096
#define ITERS     (F4_PER_SUB / TPB)   // 16

__device__ double g_mse [NBLK];
__device__ float  g_pval[NBLK];
__device__ int    g_pidx[NBLK];        // element index within image
__device__ float  g_lval[NBLK];
__device__ int    g_lidx[NBLK];
__device__ int    g_ticket = 0;

__global__ void __launch_bounds__(TPB) fused(const float4* __restrict__ pred,
                                             const float4* __restrict__ label,
                                             float* __restrict__ out)
{
    const int blk = blockIdx.x;        // 0..1023
    const int b   = blk >> 4;          // image
    const int sub = blk & 15;          // chunk within image (ascending ranges)
    const int t   = threadIdx.x;
    const int lane = t & 31;
    const int wid  = t >> 5;

    const size_t imgbase = (size_t)b * N_F4;
    int f4 = sub * F4_PER_SUB + t;     // float4 index within image, ascending

    float pv = -3.402823466e38f; int pf4 = 0;   // (max-of-4, float4 idx)
    float lv = -3.402823466e38f; int lf4 = 0;
    float m0 = 0.0f, m1 = 0.0f, m2 = 0.0f, m3 = 0.0f;

    #pragma unroll
    for (int k = 0; k < ITERS; k++) {
        const float4 p = pred [imgbase + f4];
        const float4 l = label[imgbase + f4];

        // FMNMX tree (off the carried chain) + ONE select on the chain.
        const float pm = fmaxf(fmaxf(p.x, p.y), fmaxf(p.z, p.w));
        const float lm = fmaxf(fmaxf(l.x, l.y), fmaxf(l.z, l.w));
        if (pm > pv) { pv = pm; pf4 = f4; }   // strict > keeps first f4
        if (lm > lv) { lv = lm; lf4 = f4; }

        const float dx = p.x - l.x;
        const float dy = p.y - l.y;
        const float dz = p.z - l.z;
        const float dw = p.w - l.w;
        m0 += dx * dx; m1 += dy * dy; m2 += dz * dz; m3 += dw * dw;

        f4 += TPB;
    }
    double mseD = (double)((m0 + m1) + (m2 + m3));

    // ---- warp-level reduction (no barriers) ----
    #pragma unroll
    for (int off = 16; off > 0; off >>= 1) {
        const float ovp = __shfl_down_sync(0xFFFFFFFFu, pv,  off);
        const int   oip = __shfl_down_sync(0xFFFFFFFFu, pf4, off);
        const float ovl = __shfl_down_sync(0xFFFFFFFFu, lv,  off);
        const int   oil = __shfl_down_sync(0xFFFFFFFFu, lf4, off);
        mseD += __shfl_down_sync(0xFFFFFFFFu, mseD, off);
        if (ovp > pv || (ovp == pv && oip < pf4)) { pv = ovp; pf4 = oip; }
        if (ovl > lv || (ovl == lv && oil < lf4)) { lv = ovl; lf4 = oil; }
    }

    __shared__ float  sPv[NWARP]; __shared__ int sPi[NWARP];
    __shared__ float  sLv[NWARP]; __shared__ int sLi[NWARP];
    __shared__ double sM [NWARP];
    if (lane == 0) {
        sPv[wid] = pv; sPi[wid] = pf4;
        sLv[wid] = lv; sLi[wid] = lf4;
        sM [wid] = mseD;
    }
    __syncthreads();

    __shared__ bool isLast;
    if (t == 0) {
        float bpv = sPv[0]; int bpi = sPi[0];
        float blv = sLv[0]; int bli = sLi[0];
        double bm = sM[0];
        #pragma unroll
        for (int w = 1; w < NWARP; w++) {
            if (sPv[w] > bpv || (sPv[w] == bpv && sPi[w] < bpi)) { bpv = sPv[w]; bpi = sPi[w]; }
            if (sLv[w] > blv || (sLv[w] == blv && sLi[w] < bli)) { blv = sLv[w]; bli = sLi[w]; }
            bm += sM[w];
        }
        // Resolve winning lane inside each winning float4 (first equal lane)
        {
            const float4 wp = pred[imgbase + bpi];
            int j = 3;
            if (wp.z == bpv) j = 2;
            if (wp.y == bpv) j = 1;
            if (wp.x == bpv) j = 0;
            g_pidx[blk] = bpi * 4 + j;
            g_pval[blk] = bpv;
        }
        {
            const float4 wl = label[imgbase + bli];
            int j = 3;
            if (wl.z == blv) j = 2;
            if (wl.y == blv) j = 1;
            if (wl.x == blv) j = 0;
            g_lidx[blk] = bli * 4 + j;
            g_lval[blk] = blv;
        }
        g_mse[blk] = bm;
        __threadfence();
        const int ticket = atomicAdd(&g_ticket, 1);
        isLast = (ticket == NBLK - 1);
    }
    __syncthreads();
    if (!isLast) return;

    // ---- final reduction in the last-finishing block ----
    __shared__ double fM[TPB];
    __shared__ double fIdx[BATCHES];

    {
        double s0 = 0.0;
        #pragma unroll
        for (int j = 0; j < NBLK / TPB; j++) s0 += g_mse[t * (NBLK / TPB) + j];
        fM[t] = s0;
    }

    if (t < BATCHES) {
        float ppv = -3.402823466e38f; int ppi = 0;
        float llv = -3.402823466e38f; int lli = 0;
        #pragma unroll
        for (int p = 0; p < BPB; p++) {
            const int j = t * BPB + p;   // chunks in ascending index order
            float v = g_pval[j]; int i = g_pidx[j];
            if (v > ppv || (v == ppv && i < ppi)) { ppv = v; ppi = i; }
            v = g_lval[j]; i = g_lidx[j];
            if (v > llv || (v == llv && i < lli)) { llv = v; lli = i; }
        }
        const float rp = (float)(ppi >> 9), cp = (float)(ppi & 511);
        const float rl = (float)(lli >> 9), cl = (float)(lli & 511);
        const float dr = rp - rl, dc = cp - cl;
        fIdx[t] = (double)(dr * dr) + (double)(dc * dc);
    }
    __syncthreads();

    for (int s = TPB / 2; s > 0; s >>= 1) {
        if (t < s) fM[t] += fM[t + s];
        __syncthreads();
    }
    for (int s = BATCHES / 2; s > 0; s >>= 1) {
        if (t < s) fIdx[t] += fIdx[t + s];
        __syncthreads();
    }

    if (t == 0) {
        g_ticket = 0;   // reset BEFORE the output store; next replay sees 0
        __threadfence();
        const double mseT = fM[0];
        const double il   = fIdx[0];
        const double alpha = (il != 0.0) ? (mseT / il) : 1.0;
        const double loss  = (mseT + 0.25 * alpha * il) / (double)BATCHES;
        out[0] = (float)loss;
    }
}

extern "C" void kernel_launch(void* const* d_in, const int* in_sizes, int n_in,
                              void* d_out, int out_size)
{
    (void)in_sizes; (void)n_in; (void)out_size;
    const float4* pred  = (const float4*)d_in[0];
    const float4* label = (const float4*)d_in[1];
    float* out = (float*)d_out;

    fused<<<NBLK, TPB>>>(pred, label, out);
}